// round 11
// baseline (speedup 1.0000x reference)
#include <cuda_runtime.h>

#define NN    4096

#define PED_SPEED   1.5f
#define ROBOT_SPEED 1.5f
#define K_ATTR      2.0f
#define ALPHA       10.0f
#define PED_RADIUS  0.3f
#define PED_MASS    60.0f
#define BETTA       0.71f
#define DT          0.4f
#define A_COST      4.0f
#define B_COST      1.2f
#define E_COST      0.001f
#define EPSF        1e-8f
#define LOG2E       1.4426950408889634f
#define LOG2_ALPHA  3.3219280948873623f   /* log2(10) */

#define C1C (-LOG2E / BETTA)
#define C0C ((2.0f * PED_RADIUS) * LOG2E / BETTA)
#define C0A (C0C + LOG2_ALPHA)            /* ALPHA folded into the exponent */

__device__ float2 g_pos[NN];      // 32 KB, L1-resident
__device__ float2 g_force[NN];    // accumulated repulsion (ALPHA folded)

__device__ __forceinline__ float ex2_approx(float x) {
    float r;
    asm("ex2.approx.ftz.f32 %0, %1;" : "=f"(r) : "f"(x));
    return r;
}
__device__ __forceinline__ float rsqrt_approx(float x) {
    float r;
    asm("rsqrt.approx.ftz.f32 %0, %1;" : "=f"(r) : "f"(x));
    return r;
}

// Prep: pack positions, zero force accumulators.
__global__ void __launch_bounds__(256) prep_kernel(const float4* __restrict__ state)
{
    int i = blockIdx.x * 256 + threadIdx.x;
    float4 s = state[i];
    g_pos[i]   = make_float2(s.x, s.y);
    g_force[i] = make_float2(0.0f, 0.0f);
}

// Symmetric N^2 forces: each unordered pair computed ONCE (Newton's 3rd law).
// 32x32 warp-tiles; column accumulator rotates via shfl; REDG accumulation.
__global__ void __launch_bounds__(256) force_kernel()
{
    __shared__ float2 srow[8][32];

    const int tid  = threadIdx.x;
    const int warp = tid >> 5;
    const int lane = tid & 31;
    const int b    = blockIdx.x;

    int  ti, tj;
    bool diag, extra;
    if (b < 1024) {
        ti = b >> 3;
        int s = ((b & 7) << 3) + warp + 1;       // s in 1..64
        diag  = (s == 64 && ti >= 64);           // reuse slot for diag 64..127
        extra = false;
        tj    = diag ? ti : ((ti + s) & 127);
    } else {
        ti    = ((b - 1024) << 3) + warp;        // diag tiles 0..63
        tj    = ti;
        diag  = true;
        extra = true;
    }
    const int I = ti << 5;
    const int J = tj << 5;

    const float2* __restrict__ gp = g_pos;
    const float2 pi = gp[I + lane];

    float fix = 0.0f, fiy = 0.0f;

    if (!diag) {
        // Symmetric tile: row accum in regs, column accum rotates via shfl.
        float fcx = 0.0f, fcy = 0.0f;
        int c = lane;
        #pragma unroll 8
        for (int t = 0; t < 32; t++) {
            float2 q  = gp[J + c];
            float dx  = pi.x - q.x;
            float dy  = pi.y - q.y;
            float s2  = fmaf(dx, dx, fmaf(dy, dy, EPSF));
            float rin = rsqrt_approx(s2);
            float m   = ex2_approx(fmaf(s2 * rin, C1C, C0A));
            float f   = m * rin;
            fix = fmaf(f, dx, fix);
            fiy = fmaf(f, dy, fiy);
            fcx = fmaf(f, dx, fcx);            // negated at the end
            fcy = fmaf(f, dy, fcy);
            fcx = __shfl_sync(0xffffffffu, fcx, (lane + 1) & 31);
            fcy = __shfl_sync(0xffffffffu, fcy, (lane + 1) & 31);
            c = (c + 1) & 31;
        }
        // lane l now holds the accumulator for column J+l
        atomicAdd(&g_force[J + lane].x, -fcx);
        atomicAdd(&g_force[J + lane].y, -fcy);
    } else {
        // Diagonal tile: one-sided (every ordered pair; self-pair is 0).
        int c = lane;
        #pragma unroll 8
        for (int t = 0; t < 32; t++) {
            float2 q  = gp[J + c];
            float dx  = pi.x - q.x;
            float dy  = pi.y - q.y;
            float s2  = fmaf(dx, dx, fmaf(dy, dy, EPSF));
            float rin = rsqrt_approx(s2);
            float m   = ex2_approx(fmaf(s2 * rin, C1C, C0A));
            float f   = m * rin;
            fix = fmaf(f, dx, fix);
            fiy = fmaf(f, dy, fiy);
            c = (c + 1) & 31;
        }
    }

    if (extra) {
        // Warps have distinct I-tiles: REDG rows directly.
        atomicAdd(&g_force[I + lane].x, fix);
        atomicAdd(&g_force[I + lane].y, fiy);
    } else {
        // All 8 warps share I: combine rows in smem, one REDG set per block.
        srow[warp][lane] = make_float2(fix, fiy);
        __syncthreads();
        if (warp == 0) {
            float sx = 0.0f, sy = 0.0f;
            #pragma unroll
            for (int w = 0; w < 8; w++) {
                sx += srow[w][lane].x;
                sy += srow[w][lane].y;
            }
            atomicAdd(&g_force[I + lane].x, sx);
            atomicAdd(&g_force[I + lane].y, sy);
        }
    }
}

// Finalize: attraction + propagation + cost + stacked copy. Robot pose is
// recomputed per-thread from g_force[0] (cheap, avoids any sync).
__global__ void __launch_bounds__(256) finalize_kernel(
    const float4* __restrict__ state,
    const float*  __restrict__ cost_in,
    const float4* __restrict__ stacked_in,
    const float2* __restrict__ goals,
    const float*  __restrict__ robot_init,
    float4* __restrict__ out_state,
    float*  __restrict__ out_cost,
    float4* __restrict__ out_stacked)
{
    const int i = blockIdx.x * 256 + threadIdx.x;

    // ---- Robot (row 0) pose + PG (uniform; broadcast loads) ----
    float2 gf0 = g_force[0];
    float4 s0  = state[0];
    float2 g0  = goals[0];
    float r0x, r0y, PG;
    {
        float tgx  = g0.x - s0.x;
        float tgy  = g0.y - s0.y;
        float dist = sqrtf(fmaf(tgx, tgx, tgy * tgy));
        float einv = 1.0f / (dist + EPSF);
        float Fx   = gf0.x + K_ATTR * (ROBOT_SPEED * tgx * einv - s0.z) * PED_MASS;
        float Fy   = gf0.y + K_ATTR * (ROBOT_SPEED * tgy * einv - s0.w) * PED_MASS;
        float vnx   = fmaf(Fx, DT / PED_MASS, s0.z);
        float vny   = fmaf(Fy, DT / PED_MASS, s0.w);
        float speed = sqrtf(fmaf(vnx, vnx, vny * vny));
        float sc    = fminf(1.0f, PED_SPEED / (speed + EPSF));
        vnx *= sc; vny *= sc;
        r0x = fmaf(vnx, DT, s0.x);
        r0y = fmaf(vny, DT, s0.y);
        float rix = robot_init[0];
        float riy = robot_init[1];
        float gx  = g0.x - rix;
        float gy  = g0.y - riy;
        PG = (gx * (r0x - rix) + gy * (r0y - riy)) /
             (sqrtf(fmaf(gx, gx, gy * gy)) + E_COST);
    }

    // ---- Own row ----
    float2 gf = g_force[i];
    float4 sr = state[i];
    float2 g  = goals[i];
    float tgx  = g.x - sr.x;
    float tgy  = g.y - sr.y;
    float dist = sqrtf(fmaf(tgx, tgx, tgy * tgy));
    float einv = 1.0f / (dist + EPSF);
    float ds   = (i == 0) ? ROBOT_SPEED : PED_SPEED;
    float Fx   = gf.x + K_ATTR * (ds * tgx * einv - sr.z) * PED_MASS;
    float Fy   = gf.y + K_ATTR * (ds * tgy * einv - sr.w) * PED_MASS;

    float vnx   = fmaf(Fx, DT / PED_MASS, sr.z);
    float vny   = fmaf(Fy, DT / PED_MASS, sr.w);
    float speed = sqrtf(fmaf(vnx, vnx, vny * vny));
    float sc    = fminf(1.0f, PED_SPEED / (speed + EPSF));
    vnx *= sc; vny *= sc;
    float pnx = fmaf(vnx, DT, sr.x);
    float pny = fmaf(vny, DT, sr.y);
    out_state[i] = make_float4(pnx, pny, vnx, vny);

    float ddx = pnx - r0x;
    float ddy = pny - r0y;
    float dr  = sqrtf(fmaf(ddx, ddx, fmaf(ddy, ddy, E_COST)));
    float blame = (i == 0) ? 0.0f : ex2_approx(-dr * (LOG2E / B_COST));
    out_cost[i] = cost_in[i] + (-A_COST * PG + blame);

    out_stacked[i]      = stacked_in[i];
    out_stacked[NN + i] = sr;
}

extern "C" void kernel_launch(void* const* d_in, const int* in_sizes, int n_in,
                              void* d_out, int out_size)
{
    const float4* state   = (const float4*)d_in[0];
    const float*  cost    = (const float*)d_in[1];
    const float4* stacked = (const float4*)d_in[2];
    const float2* goals   = (const float2*)d_in[3];
    const float*  rinit   = (const float*)d_in[4];

    float*  out         = (float*)d_out;
    float4* out_state   = (float4*)out;            // [0, 4N)
    float*  out_cost    = out + 4 * NN;            // [4N, 5N)
    float4* out_stacked = (float4*)(out + 5 * NN); // [5N, 13N)

    prep_kernel<<<NN / 256, 256>>>(state);
    force_kernel<<<1032, 256>>>();
    finalize_kernel<<<NN / 256, 256>>>(state, cost, stacked, goals, rinit,
                                       out_state, out_cost, out_stacked);
}

// round 12
// speedup vs baseline: 1.1359x; 1.1359x over previous
#include <cuda_runtime.h>

#define NN    4096

#define PED_SPEED   1.5f
#define ROBOT_SPEED 1.5f
#define K_ATTR      2.0f
#define ALPHA       10.0f
#define PED_RADIUS  0.3f
#define PED_MASS    60.0f
#define BETTA       0.71f
#define DT          0.4f
#define A_COST      4.0f
#define B_COST      1.2f
#define E_COST      0.001f
#define EPSF        1e-8f
#define LOG2E       1.4426950408889634f
#define LOG2_ALPHA  3.3219280948873623f   /* log2(10) */

#define C1C (-LOG2E / BETTA)
#define C0C ((2.0f * PED_RADIUS) * LOG2E / BETTA)
#define C0A (C0C + LOG2_ALPHA)            /* ALPHA folded into the exponent */

// Zero-initialized at module load; finalize_kernel re-zeroes after reading,
// so the "g_force == 0 at force_kernel entry" invariant holds on the
// correctness call AND on every graph replay. No prep kernel needed.
__device__ float2 g_force[NN];

__device__ __forceinline__ float ex2_approx(float x) {
    float r;
    asm("ex2.approx.ftz.f32 %0, %1;" : "=f"(r) : "f"(x));
    return r;
}
__device__ __forceinline__ float rsqrt_approx(float x) {
    float r;
    asm("rsqrt.approx.ftz.f32 %0, %1;" : "=f"(r) : "f"(x));
    return r;
}

// Symmetric N^2 forces: each unordered pair computed ONCE (Newton's 3rd law).
// 32x32 warp-tiles; column accumulator rotates via shfl; REDG accumulation.
// Positions read directly from state (float4, L1-resident).
__global__ void __launch_bounds__(256) force_kernel(const float4* __restrict__ state)
{
    __shared__ float2 srow[8][32];

    const int tid  = threadIdx.x;
    const int warp = tid >> 5;
    const int lane = tid & 31;
    const int b    = blockIdx.x;

    int  ti, tj;
    bool diag, extra;
    if (b < 1024) {
        ti = b >> 3;
        int s = ((b & 7) << 3) + warp + 1;       // s in 1..64
        diag  = (s == 64 && ti >= 64);           // reuse slot for diag 64..127
        extra = false;
        tj    = diag ? ti : ((ti + s) & 127);
    } else {
        ti    = ((b - 1024) << 3) + warp;        // diag tiles 0..63
        tj    = ti;
        diag  = true;
        extra = true;
    }
    const int I = ti << 5;
    const int J = tj << 5;

    const float4 sp = state[I + lane];
    const float pix = sp.x, piy = sp.y;

    float fix = 0.0f, fiy = 0.0f;

    if (!diag) {
        // Symmetric tile: row accum in regs, column accum rotates via shfl.
        float fcx = 0.0f, fcy = 0.0f;
        int c = lane;
        #pragma unroll 8
        for (int t = 0; t < 32; t++) {
            float4 q  = state[J + c];
            float dx  = pix - q.x;
            float dy  = piy - q.y;
            float s2  = fmaf(dx, dx, fmaf(dy, dy, EPSF));
            float rin = rsqrt_approx(s2);
            float m   = ex2_approx(fmaf(s2 * rin, C1C, C0A));
            float f   = m * rin;
            fix = fmaf(f, dx, fix);
            fiy = fmaf(f, dy, fiy);
            fcx = fmaf(f, dx, fcx);            // negated at the end
            fcy = fmaf(f, dy, fcy);
            fcx = __shfl_sync(0xffffffffu, fcx, (lane + 1) & 31);
            fcy = __shfl_sync(0xffffffffu, fcy, (lane + 1) & 31);
            c = (c + 1) & 31;
        }
        // lane l now holds the accumulator for column J+l
        atomicAdd(&g_force[J + lane].x, -fcx);
        atomicAdd(&g_force[J + lane].y, -fcy);
    } else {
        // Diagonal tile: one-sided (every ordered pair; self-pair is 0).
        int c = lane;
        #pragma unroll 8
        for (int t = 0; t < 32; t++) {
            float4 q  = state[J + c];
            float dx  = pix - q.x;
            float dy  = piy - q.y;
            float s2  = fmaf(dx, dx, fmaf(dy, dy, EPSF));
            float rin = rsqrt_approx(s2);
            float m   = ex2_approx(fmaf(s2 * rin, C1C, C0A));
            float f   = m * rin;
            fix = fmaf(f, dx, fix);
            fiy = fmaf(f, dy, fiy);
            c = (c + 1) & 31;
        }
    }

    if (extra) {
        // Warps have distinct I-tiles: REDG rows directly.
        atomicAdd(&g_force[I + lane].x, fix);
        atomicAdd(&g_force[I + lane].y, fiy);
    } else {
        // All 8 warps share I: combine rows in smem, one REDG set per block.
        srow[warp][lane] = make_float2(fix, fiy);
        __syncthreads();
        if (warp == 0) {
            float sx = 0.0f, sy = 0.0f;
            #pragma unroll
            for (int w = 0; w < 8; w++) {
                sx += srow[w][lane].x;
                sy += srow[w][lane].y;
            }
            atomicAdd(&g_force[I + lane].x, sx);
            atomicAdd(&g_force[I + lane].y, sy);
        }
    }
}

// Finalize: attraction + propagation + cost + stacked copy; then zero the
// force accumulator for the next graph replay. Robot pose recomputed
// per-thread from g_force[0] (cheap; avoids any extra sync/launch).
__global__ void __launch_bounds__(256) finalize_kernel(
    const float4* __restrict__ state,
    const float*  __restrict__ cost_in,
    const float4* __restrict__ stacked_in,
    const float2* __restrict__ goals,
    const float*  __restrict__ robot_init,
    float4* __restrict__ out_state,
    float*  __restrict__ out_cost,
    float4* __restrict__ out_stacked)
{
    const int i = blockIdx.x * 256 + threadIdx.x;

    // ---- Robot (row 0) pose + PG (uniform; broadcast loads) ----
    float2 gf0 = g_force[0];
    float4 s0  = state[0];
    float2 g0  = goals[0];
    float r0x, r0y, PG;
    {
        float tgx  = g0.x - s0.x;
        float tgy  = g0.y - s0.y;
        float dist = sqrtf(fmaf(tgx, tgx, tgy * tgy));
        float einv = 1.0f / (dist + EPSF);
        float Fx   = gf0.x + K_ATTR * (ROBOT_SPEED * tgx * einv - s0.z) * PED_MASS;
        float Fy   = gf0.y + K_ATTR * (ROBOT_SPEED * tgy * einv - s0.w) * PED_MASS;
        float vnx   = fmaf(Fx, DT / PED_MASS, s0.z);
        float vny   = fmaf(Fy, DT / PED_MASS, s0.w);
        float speed = sqrtf(fmaf(vnx, vnx, vny * vny));
        float sc    = fminf(1.0f, PED_SPEED / (speed + EPSF));
        vnx *= sc; vny *= sc;
        r0x = fmaf(vnx, DT, s0.x);
        r0y = fmaf(vny, DT, s0.y);
        float rix = robot_init[0];
        float riy = robot_init[1];
        float gx  = g0.x - rix;
        float gy  = g0.y - riy;
        PG = (gx * (r0x - rix) + gy * (r0y - riy)) /
             (sqrtf(fmaf(gx, gx, gy * gy)) + E_COST);
    }

    // ---- Own row ----
    float2 gf = g_force[i];
    g_force[i] = make_float2(0.0f, 0.0f);   // reset for next replay

    float4 sr = state[i];
    float2 g  = goals[i];
    float tgx  = g.x - sr.x;
    float tgy  = g.y - sr.y;
    float dist = sqrtf(fmaf(tgx, tgx, tgy * tgy));
    float einv = 1.0f / (dist + EPSF);
    float ds   = (i == 0) ? ROBOT_SPEED : PED_SPEED;
    float Fx   = gf.x + K_ATTR * (ds * tgx * einv - sr.z) * PED_MASS;
    float Fy   = gf.y + K_ATTR * (ds * tgy * einv - sr.w) * PED_MASS;

    float vnx   = fmaf(Fx, DT / PED_MASS, sr.z);
    float vny   = fmaf(Fy, DT / PED_MASS, sr.w);
    float speed = sqrtf(fmaf(vnx, vnx, vny * vny));
    float sc    = fminf(1.0f, PED_SPEED / (speed + EPSF));
    vnx *= sc; vny *= sc;
    float pnx = fmaf(vnx, DT, sr.x);
    float pny = fmaf(vny, DT, sr.y);
    out_state[i] = make_float4(pnx, pny, vnx, vny);

    float ddx = pnx - r0x;
    float ddy = pny - r0y;
    float dr  = sqrtf(fmaf(ddx, ddx, fmaf(ddy, ddy, E_COST)));
    float blame = (i == 0) ? 0.0f : ex2_approx(-dr * (LOG2E / B_COST));
    out_cost[i] = cost_in[i] + (-A_COST * PG + blame);

    out_stacked[i]      = stacked_in[i];
    out_stacked[NN + i] = sr;
}

extern "C" void kernel_launch(void* const* d_in, const int* in_sizes, int n_in,
                              void* d_out, int out_size)
{
    const float4* state   = (const float4*)d_in[0];
    const float*  cost    = (const float*)d_in[1];
    const float4* stacked = (const float4*)d_in[2];
    const float2* goals   = (const float2*)d_in[3];
    const float*  rinit   = (const float*)d_in[4];

    float*  out         = (float*)d_out;
    float4* out_state   = (float4*)out;            // [0, 4N)
    float*  out_cost    = out + 4 * NN;            // [4N, 5N)
    float4* out_stacked = (float4*)(out + 5 * NN); // [5N, 13N)

    force_kernel<<<1032, 256>>>(state);
    finalize_kernel<<<NN / 256, 256>>>(state, cost, stacked, goals, rinit,
                                       out_state, out_cost, out_stacked);
}